// round 10
// baseline (speedup 1.0000x reference)
#include <cuda_runtime.h>
#include <cuda_bf16.h>
#include <cstdint>

// Problem dims
#define NXR 8192
#define NYR 8192
#define DK  512

// Tile config: CTA 128x128, 8 warps each 32x64, K-step 64, 3 stages, 2 CTAs/SM
#define TM 128
#define TN 128
#define TK 64
#define KSTEPS (DK / TK)          // 8
#define STAGES 3

// SMEM: rows padded to 72 b16 (144B) for conflict-free ldmatrix.
#define ASTRIDE_B16 72
#define ROW_BYTES    (ASTRIDE_B16 * 2)               // 144
#define A_TILE_BYTES (TM * ROW_BYTES)                // 18432
#define B_TILE_BYTES (TN * ROW_BYTES)                // 18432
#define STAGE_BYTES  (A_TILE_BYTES + B_TILE_BYTES)   // 36864
#define TILE0_OFF    1024                            // tiles after mbarriers
#define SMEM_TOTAL   (TILE0_OFF + STAGES * STAGE_BYTES)   // 111616
#define STAGE_TX     32768                           // copied bytes per stage (256 x 128B)

// bf16 scratch + row norms (device globals: no allocation allowed)
__device__ __nv_bfloat16 g_Xb[(size_t)NXR * DK];
__device__ __nv_bfloat16 g_Yb[(size_t)NYR * DK];
__device__ float g_x2[NXR];
__device__ float g_y2[NYR];

// ---------------- PTX helpers ----------------
__device__ __forceinline__ uint32_t smem_u32(const void* p) {
    uint32_t a;
    asm("{ .reg .u64 t; cvta.to.shared.u64 t, %1; cvt.u32.u64 %0, t; }" : "=r"(a) : "l"(p));
    return a;
}

#define MBARRIER_INIT(mbar, count) \
    asm volatile("mbarrier.init.shared.b64 [%0], %1;" \
                 :: "r"((uint32_t)(mbar)), "r"((uint32_t)(count)) : "memory")

#define MBARRIER_EXPECT_TX(mbar, bytes) \
    asm volatile("mbarrier.arrive.expect_tx.shared.b64 _, [%0], %1;" \
                 :: "r"((uint32_t)(mbar)), "r"((uint32_t)(bytes)) : "memory")

#define MBARRIER_WAIT_PARITY(mbar, parity) do {                                       \
    uint32_t _mbar = (uint32_t)(mbar);                                                \
    uint32_t _parity = (uint32_t)(parity);                                            \
    uint32_t _done;                                                                   \
    asm volatile(                                                                     \
        "{\n\t.reg .pred p;\n\t"                                                      \
        "mbarrier.try_wait.parity.acquire.cta.shared::cta.b64 p, [%1], %2;\n\t"       \
        "selp.b32 %0, 1, 0, p;\n\t}"                                                  \
        : "=r"(_done) : "r"(_mbar), "r"(_parity) : "memory");                         \
    if (!_done) {                                                                     \
        asm volatile(                                                                 \
            "{\n\t.reg .pred P1;\n\t"                                                 \
            "WAIT_LOOP_%=:\n\t"                                                       \
            "mbarrier.try_wait.parity.acquire.cta.shared::cta.b64 P1, [%0], %1, 0x989680;\n\t" \
            "@P1 bra.uni WAIT_DONE_%=;\n\t"                                           \
            "bra.uni WAIT_LOOP_%=;\n\t"                                               \
            "WAIT_DONE_%=:\n\t}"                                                      \
            :: "r"(_mbar), "r"(_parity) : "memory");                                  \
    }                                                                                 \
} while (0)

#define FENCE_PROXY_ASYNC() \
    asm volatile("fence.proxy.async.shared::cta;" ::: "memory")

// One 128B bulk copy (async-proxy engine) completing on an mbarrier.
#define CP_BULK128(dst, src, mbar) \
    asm volatile("cp.async.bulk.shared::cluster.global.mbarrier::complete_tx::bytes " \
                 "[%0], [%1], 128, [%2];" \
                 :: "r"((uint32_t)(dst)), "l"(src), "r"((uint32_t)(mbar)) : "memory")

#define LDSM_X4(r, addr) \
    asm volatile("ldmatrix.sync.aligned.m8n8.x4.shared.b16 {%0,%1,%2,%3}, [%4];" \
                 : "=r"((r)[0]), "=r"((r)[1]), "=r"((r)[2]), "=r"((r)[3]) : "r"(addr))

#define MMA16816(d, a, b0, b1) \
    asm volatile("mma.sync.aligned.m16n8k16.row.col.f32.bf16.bf16.f32 " \
                 "{%0,%1,%2,%3}, {%4,%5,%6,%7}, {%8,%9}, {%0,%1,%2,%3};" \
                 : "+f"((d)[0]), "+f"((d)[1]), "+f"((d)[2]), "+f"((d)[3]) \
                 : "r"((a)[0]), "r"((a)[1]), "r"((a)[2]), "r"((a)[3]), \
                   "r"(b0), "r"(b1))

#define MMA_BURST(bb) do {                                                    \
    _Pragma("unroll")                                                         \
    for (int tm = 0; tm < 2; tm++)                                            \
        _Pragma("unroll")                                                     \
        for (int p = 0; p < 4; p++) {                                         \
            MMA16816(acc[tm][2 * p + 0], afr[tm], (bb)[p][0], (bb)[p][2]);    \
            MMA16816(acc[tm][2 * p + 1], afr[tm], (bb)[p][1], (bb)[p][3]);    \
        }                                                                     \
} while (0)

// ---------------- Prepass: f32 -> bf16 + row squared norms ----------------
__global__ void __launch_bounds__(128) rbf_prep_kernel(
    const float* __restrict__ x, const float* __restrict__ y) {
    __shared__ float red[4];
    int b = blockIdx.x;
    int t = threadIdx.x;
    const float* src;
    __nv_bfloat16* dst;
    float* nrm;
    int row;
    if (b < NXR) { row = b;       src = x + (size_t)row * DK; dst = g_Xb + (size_t)row * DK; nrm = g_x2; }
    else         { row = b - NXR; src = y + (size_t)row * DK; dst = g_Yb + (size_t)row * DK; nrm = g_y2; }

    float4 v = reinterpret_cast<const float4*>(src)[t];
    float s = v.x * v.x + v.y * v.y + v.z * v.z + v.w * v.w;
    __nv_bfloat162 h0 = __floats2bfloat162_rn(v.x, v.y);
    __nv_bfloat162 h1 = __floats2bfloat162_rn(v.z, v.w);
    reinterpret_cast<__nv_bfloat162*>(dst)[t * 2 + 0] = h0;
    reinterpret_cast<__nv_bfloat162*>(dst)[t * 2 + 1] = h1;

    #pragma unroll
    for (int o = 16; o; o >>= 1) s += __shfl_xor_sync(0xffffffffu, s, o);
    if ((t & 31) == 0) red[t >> 5] = s;
    __syncthreads();
    if (t == 0) nrm[row] = red[0] + red[1] + red[2] + red[3];
}

// ---------------- Main kernel: bulk-async pipelined GEMM + RBF epilogue ----------------
__global__ void __launch_bounds__(256, 2) rbf_gemm_kernel(
    float* __restrict__ out, const float* __restrict__ gamma_p) {
    extern __shared__ __align__(1024) char smem[];
    const uint32_t sb = smem_u32(smem);
    const int tid = threadIdx.x;
    const int wid = tid >> 5;
    const int lid = tid & 31;
    const int wm = wid & 3;            // warp row: 32-row slab (4)
    const int wn = wid >> 2;           // warp col: 64-col slab (2)
    const int mbase = blockIdx.y * TM;
    const int nbase = blockIdx.x * TN;

    // mbarriers: full[s] at sb + s*8
    if (tid == 0) {
        MBARRIER_INIT(sb + 0, 1);
        MBARRIER_INIT(sb + 8, 1);
        MBARRIER_INIT(sb + 16, 1);
        FENCE_PROXY_ASYNC();
        MBARRIER_EXPECT_TX(sb + 0, STAGE_TX);
        MBARRIER_EXPECT_TX(sb + 8, STAGE_TX);
    }
    __syncthreads();

    // Per-thread copy role: threads 0..127 -> A row (tid), 128..255 -> B row (tid-128).
    const int crow = tid & 127;
    const __nv_bfloat16* csrc =
        (tid < 128 ? g_Xb + (size_t)(mbase + crow) * DK
                   : g_Yb + (size_t)(nbase + crow) * DK);
    const uint32_t cdst = sb + TILE0_OFF + (tid < 128 ? 0 : A_TILE_BYTES)
                        + (uint32_t)crow * ROW_BYTES;

    // Prologue: issue stages 0 and 1 (one 128B copy per thread per stage).
    CP_BULK128(cdst + 0 * STAGE_BYTES, csrc + 0 * TK, sb + 0);
    CP_BULK128(cdst + 1 * STAGE_BYTES, csrc + 1 * TK, sb + 8);

    float acc[2][8][4];
    #pragma unroll
    for (int i = 0; i < 2; i++)
        #pragma unroll
        for (int j = 0; j < 8; j++)
            #pragma unroll
            for (int q = 0; q < 4; q++) acc[i][j][q] = 0.0f;

    const int lrow = lid & 15;
    const int lhalf = lid >> 4;
    const uint32_t aoff = sb + TILE0_OFF
                        + (uint32_t)((wm * 32 + lrow) * ROW_BYTES + lhalf * 16);
    const uint32_t boff = sb + TILE0_OFF + A_TILE_BYTES
                        + (uint32_t)((wn * 64 + lrow) * ROW_BYTES + lhalf * 16);

    // Wait stage 0 and prime b0 = B(stage0, kk=0).
    MBARRIER_WAIT_PARITY(sb + 0, 0);
    uint32_t b0[4][4], b1[4][4], afr[2][4];
    #pragma unroll
    for (int p = 0; p < 4; p++)
        LDSM_X4(b0[p], boff + p * (16 * ROW_BYTES));

    #pragma unroll
    for (int k = 0; k < KSTEPS; k++) {
        const uint32_t stoff = (uint32_t)((k % STAGES) * STAGE_BYTES);

        // kk=0: load B(kk=1)->b1, A(kk=0); MMA on b0
        #pragma unroll
        for (int p = 0; p < 4; p++)
            LDSM_X4(b1[p], boff + stoff + 1 * 32 + p * (16 * ROW_BYTES));
        #pragma unroll
        for (int tm = 0; tm < 2; tm++)
            LDSM_X4(afr[tm], aoff + stoff + 0 * 32 + tm * (16 * ROW_BYTES));
        MMA_BURST(b0);

        // kk=1: load B(kk=2)->b0, A(kk=1); MMA on b1
        #pragma unroll
        for (int p = 0; p < 4; p++)
            LDSM_X4(b0[p], boff + stoff + 2 * 32 + p * (16 * ROW_BYTES));
        #pragma unroll
        for (int tm = 0; tm < 2; tm++)
            LDSM_X4(afr[tm], aoff + stoff + 1 * 32 + tm * (16 * ROW_BYTES));
        MMA_BURST(b1);

        // kk=2: load B(kk=3)->b1, A(kk=2); MMA on b0
        #pragma unroll
        for (int p = 0; p < 4; p++)
            LDSM_X4(b1[p], boff + stoff + 3 * 32 + p * (16 * ROW_BYTES));
        #pragma unroll
        for (int tm = 0; tm < 2; tm++)
            LDSM_X4(afr[tm], aoff + stoff + 2 * 32 + tm * (16 * ROW_BYTES));
        MMA_BURST(b0);

        // kk=3: A read pre-sync (stage k still valid).
        #pragma unroll
        for (int tm = 0; tm < 2; tm++)
            LDSM_X4(afr[tm], aoff + stoff + 3 * 32 + tm * (16 * ROW_BYTES));

        // Refill slot (k+2)%3 with stage k+2 (its old contents, stage k-1,
        // were fully read before iter k-1's sync).
        if (k + 2 < KSTEPS) {
            const uint32_t mb = sb + (uint32_t)(((k + 2) % STAGES) * 8);
            if (tid == 0) MBARRIER_EXPECT_TX(mb, STAGE_TX);
        }
        __syncthreads();
        if (k + 2 < KSTEPS) {
            const uint32_t mb = sb + (uint32_t)(((k + 2) % STAGES) * 8);
            CP_BULK128(cdst + (uint32_t)(((k + 2) % STAGES) * STAGE_BYTES),
                       csrc + (k + 2) * TK, mb);
        }

        // Wait stage k+1, prime b0 from it (hides under the MMA burst below).
        if (k + 1 < KSTEPS) {
            MBARRIER_WAIT_PARITY(sb + (uint32_t)(((k + 1) % STAGES) * 8),
                                 ((k + 1) / STAGES) & 1);
            const uint32_t snoff = (uint32_t)(((k + 1) % STAGES) * STAGE_BYTES);
            #pragma unroll
            for (int p = 0; p < 4; p++)
                LDSM_X4(b0[p], boff + snoff + p * (16 * ROW_BYTES));
        }
        MMA_BURST(b1);
    }

    // ---------------- Epilogue ----------------
    const float gam = __ldg(gamma_p);
    #pragma unroll
    for (int tm = 0; tm < 2; tm++) {
        const int m0 = mbase + wm * 32 + tm * 16 + (lid >> 2);
        const float x2a = g_x2[m0];
        const float x2b = g_x2[m0 + 8];
        #pragma unroll
        for (int nn = 0; nn < 8; nn++) {
            const int n0 = nbase + wn * 64 + nn * 8 + (lid & 3) * 2;
            const float y2a = g_y2[n0];
            const float y2b = g_y2[n0 + 1];
            const float* c = acc[tm][nn];
            float2 v0, v1;
            v0.x = __expf(-gam * fmaxf(x2a + y2a - 2.0f * c[0], 0.0f));
            v0.y = __expf(-gam * fmaxf(x2a + y2b - 2.0f * c[1], 0.0f));
            v1.x = __expf(-gam * fmaxf(x2b + y2a - 2.0f * c[2], 0.0f));
            v1.y = __expf(-gam * fmaxf(x2b + y2b - 2.0f * c[3], 0.0f));
            *reinterpret_cast<float2*>(out + (size_t)m0 * NYR + n0) = v0;
            *reinterpret_cast<float2*>(out + (size_t)(m0 + 8) * NYR + n0) = v1;
        }
    }
}

extern "C" void kernel_launch(void* const* d_in, const int* in_sizes, int n_in,
                              void* d_out, int out_size) {
    const float* x = (const float*)d_in[0];
    const float* y = (const float*)d_in[1];
    const float* gamma = (const float*)d_in[2];
    float* out = (float*)d_out;

    rbf_prep_kernel<<<NXR + NYR, 128>>>(x, y);

    cudaFuncSetAttribute(rbf_gemm_kernel,
                         cudaFuncAttributeMaxDynamicSharedMemorySize, SMEM_TOTAL);
    dim3 grid(NYR / TN, NXR / TM);
    rbf_gemm_kernel<<<grid, 256, SMEM_TOTAL>>>(out, gamma);
}

// round 11
// speedup vs baseline: 1.2078x; 1.2078x over previous
#include <cuda_runtime.h>
#include <cuda_bf16.h>
#include <cstdint>

// Problem dims
#define NXR 8192
#define NYR 8192
#define DK  512

// Tile config: CTA 128x128, 8 warps each 32x64, K-step 64, 3 stages, 2 CTAs/SM
#define TM 128
#define TN 128
#define TK 64
#define KSTEPS (DK / TK)          // 8
#define STAGES 3

// SMEM: rows padded to 72 b16 (144B) for conflict-free ldmatrix.
#define ASTRIDE_B16 72
#define ROW_BYTES    (ASTRIDE_B16 * 2)               // 144
#define A_TILE_BYTES (TM * ROW_BYTES)                // 18432
#define B_TILE_BYTES (TN * ROW_BYTES)                // 18432
#define STAGE_BYTES  (A_TILE_BYTES + B_TILE_BYTES)   // 36864
#define SMEM_TOTAL   (STAGES * STAGE_BYTES)          // 110592

// bf16 scratch + row norms (device globals: no allocation allowed)
__device__ __nv_bfloat16 g_Xb[(size_t)NXR * DK];
__device__ __nv_bfloat16 g_Yb[(size_t)NYR * DK];
__device__ float g_x2[NXR];
__device__ float g_y2[NYR];

// ---------------- PTX helpers ----------------
__device__ __forceinline__ uint32_t smem_u32(const void* p) {
    uint32_t a;
    asm("{ .reg .u64 t; cvta.to.shared.u64 t, %1; cvt.u32.u64 %0, t; }" : "=r"(a) : "l"(p));
    return a;
}

#define CP_ASYNC16(saddr, gptr) \
    asm volatile("cp.async.cg.shared.global [%0], [%1], 16;" \
                 :: "r"(saddr), "l"(gptr) : "memory")

#define CP_COMMIT() asm volatile("cp.async.commit_group;" ::: "memory")
#define CP_WAIT(n)  asm volatile("cp.async.wait_group %0;" :: "n"(n) : "memory")

#define LDSM_X4(r, addr) \
    asm volatile("ldmatrix.sync.aligned.m8n8.x4.shared.b16 {%0,%1,%2,%3}, [%4];" \
                 : "=r"((r)[0]), "=r"((r)[1]), "=r"((r)[2]), "=r"((r)[3]) : "r"(addr))

#define MMA16816(d, a, b0, b1) \
    asm volatile("mma.sync.aligned.m16n8k16.row.col.f32.bf16.bf16.f32 " \
                 "{%0,%1,%2,%3}, {%4,%5,%6,%7}, {%8,%9}, {%0,%1,%2,%3};" \
                 : "+f"((d)[0]), "+f"((d)[1]), "+f"((d)[2]), "+f"((d)[3]) \
                 : "r"((a)[0]), "r"((a)[1]), "r"((a)[2]), "r"((a)[3]), \
                   "r"(b0), "r"(b1))

// 8 cp.asyncs for one stage; only 2 live pointers, all else immediates.
#define LOAD_STAGE(ls, apb, bpb, so0) do {                                    \
    CP_ASYNC16((ls) + (so0),                       (apb));                    \
    CP_ASYNC16((ls) + (so0) + 32 * ROW_BYTES,      (apb) + 32 * DK);          \
    CP_ASYNC16((ls) + (so0) + 64 * ROW_BYTES,      (apb) + 64 * DK);          \
    CP_ASYNC16((ls) + (so0) + 96 * ROW_BYTES,      (apb) + 96 * DK);          \
    CP_ASYNC16((ls) + A_TILE_BYTES + (so0),                  (bpb));          \
    CP_ASYNC16((ls) + A_TILE_BYTES + (so0) + 32 * ROW_BYTES, (bpb) + 32 * DK);\
    CP_ASYNC16((ls) + A_TILE_BYTES + (so0) + 64 * ROW_BYTES, (bpb) + 64 * DK);\
    CP_ASYNC16((ls) + A_TILE_BYTES + (so0) + 96 * ROW_BYTES, (bpb) + 96 * DK);\
} while (0)

#define MMA_BURST(bb) do {                                                    \
    _Pragma("unroll")                                                         \
    for (int tm = 0; tm < 2; tm++)                                            \
        _Pragma("unroll")                                                     \
        for (int p = 0; p < 4; p++) {                                         \
            MMA16816(acc[tm][2 * p + 0], afr[tm], (bb)[p][0], (bb)[p][2]);    \
            MMA16816(acc[tm][2 * p + 1], afr[tm], (bb)[p][1], (bb)[p][3]);    \
        }                                                                     \
} while (0)

// ---------------- Prepass: f32 -> bf16 + row squared norms ----------------
__global__ void __launch_bounds__(128) rbf_prep_kernel(
    const float* __restrict__ x, const float* __restrict__ y) {
    __shared__ float red[4];
    int b = blockIdx.x;
    int t = threadIdx.x;
    const float* src;
    __nv_bfloat16* dst;
    float* nrm;
    int row;
    if (b < NXR) { row = b;       src = x + (size_t)row * DK; dst = g_Xb + (size_t)row * DK; nrm = g_x2; }
    else         { row = b - NXR; src = y + (size_t)row * DK; dst = g_Yb + (size_t)row * DK; nrm = g_y2; }

    float4 v = reinterpret_cast<const float4*>(src)[t];
    float s = v.x * v.x + v.y * v.y + v.z * v.z + v.w * v.w;
    __nv_bfloat162 h0 = __floats2bfloat162_rn(v.x, v.y);
    __nv_bfloat162 h1 = __floats2bfloat162_rn(v.z, v.w);
    reinterpret_cast<__nv_bfloat162*>(dst)[t * 2 + 0] = h0;
    reinterpret_cast<__nv_bfloat162*>(dst)[t * 2 + 1] = h1;

    #pragma unroll
    for (int o = 16; o; o >>= 1) s += __shfl_xor_sync(0xffffffffu, s, o);
    if ((t & 31) == 0) red[t >> 5] = s;
    __syncthreads();
    if (t == 0) nrm[row] = red[0] + red[1] + red[2] + red[3];
}

// ---------------- Main kernel: fully-unrolled pipelined GEMM + RBF epilogue ----------------
__global__ void __launch_bounds__(256, 2) rbf_gemm_kernel(
    float* __restrict__ out, const float* __restrict__ gamma_p) {
    extern __shared__ char smem[];
    const uint32_t sb = smem_u32(smem);
    const int tid = threadIdx.x;
    const int wid = tid >> 5;
    const int lid = tid & 31;
    const int wm = wid & 3;            // warp row: 32-row slab (4)
    const int wn = wid >> 2;           // warp col: 64-col slab (2)
    const int mbase = blockIdx.y * TM;
    const int nbase = blockIdx.x * TN;

    // cp.async base assignment: row lr0 = tid>>3 (0..31), seg ls0 = tid&7.
    const int lr0 = tid >> 3, ls0 = tid & 7;
    const __nv_bfloat16* apb = g_Xb + (size_t)(mbase + lr0) * DK + ls0 * 8;
    const __nv_bfloat16* bpb = g_Yb + (size_t)(nbase + lr0) * DK + ls0 * 8;
    const uint32_t so0 = (uint32_t)(lr0 * ROW_BYTES + ls0 * 16);

    #pragma unroll
    for (int s = 0; s < STAGES - 1; s++) {
        LOAD_STAGE(sb + s * STAGE_BYTES, apb, bpb, so0);
        CP_COMMIT();
        apb += TK; bpb += TK;
    }

    float acc[2][8][4];
    #pragma unroll
    for (int i = 0; i < 2; i++)
        #pragma unroll
        for (int j = 0; j < 8; j++)
            #pragma unroll
            for (int q = 0; q < 4; q++) acc[i][j][q] = 0.0f;

    const int lrow = lid & 15;
    const int lhalf = lid >> 4;
    const uint32_t aoff = sb + (uint32_t)((wm * 32 + lrow) * ROW_BYTES + lhalf * 16);
    const uint32_t boff = sb + A_TILE_BYTES
                        + (uint32_t)((wn * 64 + lrow) * ROW_BYTES + lhalf * 16);

    // Prologue: stage 0 landed; prime b0 = B(stage0, kk=0).
    CP_WAIT(STAGES - 2);
    __syncthreads();
    uint32_t b0[4][4], b1[4][4], afr[2][4];
    #pragma unroll
    for (int p = 0; p < 4; p++)
        LDSM_X4(b0[p], boff + p * (16 * ROW_BYTES));

    #pragma unroll
    for (int k = 0; k < KSTEPS; k++) {                 // FULLY UNROLLED
        const uint32_t stoff = (uint32_t)((k % STAGES) * STAGE_BYTES);  // imm

        // kk=0: load B(kk=1)->b1, A(kk=0); MMA on b0
        #pragma unroll
        for (int p = 0; p < 4; p++)
            LDSM_X4(b1[p], boff + stoff + 1 * 32 + p * (16 * ROW_BYTES));
        #pragma unroll
        for (int tm = 0; tm < 2; tm++)
            LDSM_X4(afr[tm], aoff + stoff + 0 * 32 + tm * (16 * ROW_BYTES));
        MMA_BURST(b0);

        // Issue next-stage cp.asyncs (drain under MMA bursts).
        if (k + STAGES - 1 < KSTEPS) {
            LOAD_STAGE(sb + (uint32_t)(((k + STAGES - 1) % STAGES) * STAGE_BYTES),
                       apb, bpb, so0);
            apb += TK; bpb += TK;
        }
        CP_COMMIT();

        // kk=1: load B(kk=2)->b0, A(kk=1); MMA on b1
        #pragma unroll
        for (int p = 0; p < 4; p++)
            LDSM_X4(b0[p], boff + stoff + 2 * 32 + p * (16 * ROW_BYTES));
        #pragma unroll
        for (int tm = 0; tm < 2; tm++)
            LDSM_X4(afr[tm], aoff + stoff + 1 * 32 + tm * (16 * ROW_BYTES));
        MMA_BURST(b1);

        // kk=2: load B(kk=3)->b1, A(kk=2); MMA on b0
        #pragma unroll
        for (int p = 0; p < 4; p++)
            LDSM_X4(b1[p], boff + stoff + 3 * 32 + p * (16 * ROW_BYTES));
        #pragma unroll
        for (int tm = 0; tm < 2; tm++)
            LDSM_X4(afr[tm], aoff + stoff + 2 * 32 + tm * (16 * ROW_BYTES));
        MMA_BURST(b0);

        // kk=3: A read pre-sync; wait+sync; prime b0 from stage k+1 (hidden
        // under the MMA burst below).
        #pragma unroll
        for (int tm = 0; tm < 2; tm++)
            LDSM_X4(afr[tm], aoff + stoff + 3 * 32 + tm * (16 * ROW_BYTES));
        CP_WAIT(STAGES - 2);
        __syncthreads();
        if (k + 1 < KSTEPS) {
            const uint32_t snoff = (uint32_t)(((k + 1) % STAGES) * STAGE_BYTES);
            #pragma unroll
            for (int p = 0; p < 4; p++)
                LDSM_X4(b0[p], boff + snoff + p * (16 * ROW_BYTES));
        }
        MMA_BURST(b1);
    }

    // ---------------- Epilogue ----------------
    const float gam = __ldg(gamma_p);
    #pragma unroll
    for (int tm = 0; tm < 2; tm++) {
        const int m0 = mbase + wm * 32 + tm * 16 + (lid >> 2);
        const float x2a = g_x2[m0];
        const float x2b = g_x2[m0 + 8];
        #pragma unroll
        for (int nn = 0; nn < 8; nn++) {
            const int n0 = nbase + wn * 64 + nn * 8 + (lid & 3) * 2;
            const float y2a = g_y2[n0];
            const float y2b = g_y2[n0 + 1];
            const float* c = acc[tm][nn];
            float2 v0, v1;
            v0.x = __expf(-gam * fmaxf(x2a + y2a - 2.0f * c[0], 0.0f));
            v0.y = __expf(-gam * fmaxf(x2a + y2b - 2.0f * c[1], 0.0f));
            v1.x = __expf(-gam * fmaxf(x2b + y2a - 2.0f * c[2], 0.0f));
            v1.y = __expf(-gam * fmaxf(x2b + y2b - 2.0f * c[3], 0.0f));
            *reinterpret_cast<float2*>(out + (size_t)m0 * NYR + n0) = v0;
            *reinterpret_cast<float2*>(out + (size_t)(m0 + 8) * NYR + n0) = v1;
        }
    }
}

extern "C" void kernel_launch(void* const* d_in, const int* in_sizes, int n_in,
                              void* d_out, int out_size) {
    const float* x = (const float*)d_in[0];
    const float* y = (const float*)d_in[1];
    const float* gamma = (const float*)d_in[2];
    float* out = (float*)d_out;

    rbf_prep_kernel<<<NXR + NYR, 128>>>(x, y);

    cudaFuncSetAttribute(rbf_gemm_kernel,
                         cudaFuncAttributeMaxDynamicSharedMemorySize, SMEM_TOTAL);
    dim3 grid(NYR / TN, NXR / TM);
    rbf_gemm_kernel<<<grid, 256, SMEM_TOTAL>>>(out, gamma);
}

// round 13
// speedup vs baseline: 1.4273x; 1.1817x over previous
#include <cuda_runtime.h>
#include <cuda_bf16.h>
#include <cstdint>

// Problem dims
#define NXR 8192
#define NYR 8192
#define DK  512

// Tile config: CTA 128x128, 8 warps each 32x64, K-step 64, 3 stages, 2 CTAs/SM
#define TM 128
#define TN 128
#define TK 64
#define KSTEPS (DK / TK)          // 8
#define STAGES 3

// SMEM: unpadded 128B rows, XOR-swizzled 16B chunks (pre-swizzled in global).
#define TILE_BYTES  16384                       // 128 rows x 128 B
#define STAGE_BYTES (2 * TILE_BYTES)            // A + B = 32768
#define STAGE_TX    STAGE_BYTES
#define TILE0_OFF   1024
#define SMEM_TOTAL  (TILE0_OFF + STAGES * STAGE_BYTES)   // 99328

// bf16 scratch, K-chunk-tiled + swizzled: elem = (kc*NXR + row)*64 + (c16^(row&7))*8 + in16
__device__ __nv_bfloat16 g_Xb[(size_t)NXR * DK];
__device__ __nv_bfloat16 g_Yb[(size_t)NYR * DK];
__device__ float g_x2[NXR];
__device__ float g_y2[NYR];

// ---------------- PTX helpers ----------------
__device__ __forceinline__ uint32_t smem_u32(const void* p) {
    uint32_t a;
    asm("{ .reg .u64 t; cvta.to.shared.u64 t, %1; cvt.u32.u64 %0, t; }" : "=r"(a) : "l"(p));
    return a;
}

#define MBARRIER_INIT(mbar, count) \
    asm volatile("mbarrier.init.shared.b64 [%0], %1;" \
                 :: "r"((uint32_t)(mbar)), "r"((uint32_t)(count)) : "memory")

#define MBARRIER_EXPECT_TX(mbar, bytes) \
    asm volatile("mbarrier.arrive.expect_tx.shared.b64 _, [%0], %1;" \
                 :: "r"((uint32_t)(mbar)), "r"((uint32_t)(bytes)) : "memory")

#define MBARRIER_WAIT_PARITY(mbar, parity) do {                                       \
    uint32_t _mbar = (uint32_t)(mbar);                                                \
    uint32_t _parity = (uint32_t)(parity);                                            \
    uint32_t _done;                                                                   \
    asm volatile(                                                                     \
        "{\n\t.reg .pred p;\n\t"                                                      \
        "mbarrier.try_wait.parity.acquire.cta.shared::cta.b64 p, [%1], %2;\n\t"       \
        "selp.b32 %0, 1, 0, p;\n\t}"                                                  \
        : "=r"(_done) : "r"(_mbar), "r"(_parity) : "memory");                         \
    if (!_done) {                                                                     \
        asm volatile(                                                                 \
            "{\n\t.reg .pred P1;\n\t"                                                 \
            "WAIT_LOOP_%=:\n\t"                                                       \
            "mbarrier.try_wait.parity.acquire.cta.shared::cta.b64 P1, [%0], %1, 0x989680;\n\t" \
            "@P1 bra.uni WAIT_DONE_%=;\n\t"                                           \
            "bra.uni WAIT_LOOP_%=;\n\t"                                               \
            "WAIT_DONE_%=:\n\t}"                                                      \
            :: "r"(_mbar), "r"(_parity) : "memory");                                  \
    }                                                                                 \
} while (0)

#define FENCE_PROXY_ASYNC() \
    asm volatile("fence.proxy.async.shared::cta;" ::: "memory")

#define CP_BULK(dst, src, bytes, mbar) \
    asm volatile("cp.async.bulk.shared::cluster.global.mbarrier::complete_tx::bytes " \
                 "[%0], [%1], %2, [%3];" \
                 :: "r"((uint32_t)(dst)), "l"(src), "r"((uint32_t)(bytes)), \
                    "r"((uint32_t)(mbar)) : "memory")

#define LDSM_X4(r, addr) \
    asm volatile("ldmatrix.sync.aligned.m8n8.x4.shared.b16 {%0,%1,%2,%3}, [%4];" \
                 : "=r"((r)[0]), "=r"((r)[1]), "=r"((r)[2]), "=r"((r)[3]) : "r"(addr))

#define MMA16816(d, a, b0, b1) \
    asm volatile("mma.sync.aligned.m16n8k16.row.col.f32.bf16.bf16.f32 " \
                 "{%0,%1,%2,%3}, {%4,%5,%6,%7}, {%8,%9}, {%0,%1,%2,%3};" \
                 : "+f"((d)[0]), "+f"((d)[1]), "+f"((d)[2]), "+f"((d)[3]) \
                 : "r"((a)[0]), "r"((a)[1]), "r"((a)[2]), "r"((a)[3]), \
                   "r"(b0), "r"(b1))

#define MMA_BURST(bb) do {                                                    \
    _Pragma("unroll")                                                         \
    for (int tm = 0; tm < 2; tm++)                                            \
        _Pragma("unroll")                                                     \
        for (int p = 0; p < 4; p++) {                                         \
            MMA16816(acc[tm][2 * p + 0], afr[tm], (bb)[p][0], (bb)[p][2]);    \
            MMA16816(acc[tm][2 * p + 1], afr[tm], (bb)[p][1], (bb)[p][3]);    \
        }                                                                     \
} while (0)

// ---------------- Prepass: f32 -> swizzled K-tiled bf16 + row norms ----------------
__global__ void __launch_bounds__(128) rbf_prep_kernel(
    const float* __restrict__ x, const float* __restrict__ y) {
    __shared__ float red[4];
    int b = blockIdx.x;
    int t = threadIdx.x;
    const float* src;
    __nv_bfloat16* dst;
    float* nrm;
    int row;
    if (b < NXR) { row = b;       src = x + (size_t)row * DK; dst = g_Xb; nrm = g_x2; }
    else         { row = b - NXR; src = y + (size_t)row * DK; dst = g_Yb; nrm = g_y2; }

    float4 v = reinterpret_cast<const float4*>(src)[t];   // cols 4t..4t+3
    float s = v.x * v.x + v.y * v.y + v.z * v.z + v.w * v.w;

    // Swizzled K-tiled destination: kc = t>>4, cc = (t&15)*4, c16 = cc>>3
    const int kc = t >> 4;
    const int cc = (t & 15) * 4;
    const int c16 = cc >> 3;
    const int sw = c16 ^ (row & 7);
    const size_t elem = ((size_t)kc * NXR + row) * 64 + sw * 8 + (cc & 7);
    __nv_bfloat162* d2 = reinterpret_cast<__nv_bfloat162*>(dst + elem);
    d2[0] = __floats2bfloat162_rn(v.x, v.y);
    d2[1] = __floats2bfloat162_rn(v.z, v.w);

    #pragma unroll
    for (int o = 16; o; o >>= 1) s += __shfl_xor_sync(0xffffffffu, s, o);
    if ((t & 31) == 0) red[t >> 5] = s;
    __syncthreads();
    if (t == 0) nrm[row] = red[0] + red[1] + red[2] + red[3];
}

// ---------------- Main kernel: bulk-copy pipelined GEMM + RBF epilogue ----------------
__global__ void __launch_bounds__(256, 2) rbf_gemm_kernel(
    float* __restrict__ out, const float* __restrict__ gamma_p) {
    extern __shared__ __align__(1024) char smem[];
    const uint32_t sb = smem_u32(smem);
    const int tid = threadIdx.x;
    const int wid = tid >> 5;
    const int lid = tid & 31;
    const int wm = wid & 3;            // warp row: 32-row slab (4)
    const int wn = wid >> 2;           // warp col: 64-col slab (2)
    const int mbase = blockIdx.y * TM;
    const int nbase = blockIdx.x * TN;

    // mbarriers at sb+0,8,16
    if (tid == 0) {
        MBARRIER_INIT(sb + 0, 1);
        MBARRIER_INIT(sb + 8, 1);
        MBARRIER_INIT(sb + 16, 1);
        FENCE_PROXY_ASYNC();
    }
    __syncthreads();

    // Global sources: A stage kc at g_Xb + (kc*NXR + mbase)*64, 16 KB contiguous.
    const __nv_bfloat16* asrc = g_Xb + (size_t)mbase * 64;
    const __nv_bfloat16* bsrc = g_Yb + (size_t)nbase * 64;
    const uint32_t tileA = sb + TILE0_OFF;           // + s*STAGE_BYTES
    const uint32_t tileB = sb + TILE0_OFF + TILE_BYTES;

    if (tid == 0) {
        MBARRIER_EXPECT_TX(sb + 0, STAGE_TX);
        CP_BULK(tileA + 0 * STAGE_BYTES, asrc + (size_t)0 * NXR * 64, TILE_BYTES, sb + 0);
        CP_BULK(tileB + 0 * STAGE_BYTES, bsrc + (size_t)0 * NYR * 64, TILE_BYTES, sb + 0);
        MBARRIER_EXPECT_TX(sb + 8, STAGE_TX);
        CP_BULK(tileA + 1 * STAGE_BYTES, asrc + (size_t)1 * NXR * 64, TILE_BYTES, sb + 8);
        CP_BULK(tileB + 1 * STAGE_BYTES, bsrc + (size_t)1 * NYR * 64, TILE_BYTES, sb + 8);
    }

    float acc[2][8][4];
    #pragma unroll
    for (int i = 0; i < 2; i++)
        #pragma unroll
        for (int j = 0; j < 8; j++)
            #pragma unroll
            for (int q = 0; q < 4; q++) acc[i][j][q] = 0.0f;

    // ldsm addressing: addr = tile + row*128 + ((kk*2+lhalf)^(lrow&7))*16
    const int lrow = lid & 15;
    const int lhalf = lid >> 4;
    const int r7 = lrow & 7;
    const uint32_t c0 = (uint32_t)(((0 + lhalf) ^ r7) * 16);
    const uint32_t c1 = (uint32_t)(((2 + lhalf) ^ r7) * 16);
    const uint32_t c2 = (uint32_t)(((4 + lhalf) ^ r7) * 16);
    const uint32_t c3 = (uint32_t)(((6 + lhalf) ^ r7) * 16);
    const uint32_t abase = tileA + (uint32_t)((wm * 32 + lrow) * 128);
    const uint32_t bbase = tileB + (uint32_t)((wn * 64 + lrow) * 128);

    // Wait stage 0; prime b0 = B(stage0, kk=0).
    MBARRIER_WAIT_PARITY(sb + 0, 0);
    uint32_t b0[4][4], b1[4][4], afr[2][4];
    #pragma unroll
    for (int p = 0; p < 4; p++)
        LDSM_X4(b0[p], bbase + c0 + p * (16 * 128));

    #pragma unroll
    for (int k = 0; k < KSTEPS; k++) {                 // FULLY UNROLLED
        const uint32_t stoff = (uint32_t)((k % STAGES) * STAGE_BYTES);

        // kk=0: load B(kk=1)->b1, A(kk=0); MMA on b0
        #pragma unroll
        for (int p = 0; p < 4; p++)
            LDSM_X4(b1[p], bbase + stoff + c1 + p * (16 * 128));
        #pragma unroll
        for (int tm = 0; tm < 2; tm++)
            LDSM_X4(afr[tm], abase + stoff + c0 + tm * (16 * 128));
        MMA_BURST(b0);

        // Issue stage k+2 (slot held stage k-1; dead since iter k-1's sync).
        if (k + 2 < KSTEPS && tid == 0) {
            const uint32_t mb = sb + (uint32_t)(((k + 2) % STAGES) * 8);
            const uint32_t soff = (uint32_t)(((k + 2) % STAGES) * STAGE_BYTES);
            FENCE_PROXY_ASYNC();
            MBARRIER_EXPECT_TX(mb, STAGE_TX);
            CP_BULK(tileA + soff, asrc + (size_t)(k + 2) * NXR * 64, TILE_BYTES, mb);
            CP_BULK(tileB + soff, bsrc + (size_t)(k + 2) * NYR * 64, TILE_BYTES, mb);
        }

        // kk=1: load B(kk=2)->b0, A(kk=1); MMA on b1
        #pragma unroll
        for (int p = 0; p < 4; p++)
            LDSM_X4(b0[p], bbase + stoff + c2 + p * (16 * 128));
        #pragma unroll
        for (int tm = 0; tm < 2; tm++)
            LDSM_X4(afr[tm], abase + stoff + c1 + tm * (16 * 128));
        MMA_BURST(b1);

        // kk=2: load B(kk=3)->b1, A(kk=2); MMA on b0
        #pragma unroll
        for (int p = 0; p < 4; p++)
            LDSM_X4(b1[p], bbase + stoff + c3 + p * (16 * 128));
        #pragma unroll
        for (int tm = 0; tm < 2; tm++)
            LDSM_X4(afr[tm], abase + stoff + c2 + tm * (16 * 128));
        MMA_BURST(b0);

        // kk=3: A pre-sync; sync (slot-reuse fence); wait stage k+1; prime b0.
        #pragma unroll
        for (int tm = 0; tm < 2; tm++)
            LDSM_X4(afr[tm], abase + stoff + c3 + tm * (16 * 128));
        __syncthreads();
        if (k + 1 < KSTEPS) {
            MBARRIER_WAIT_PARITY(sb + (uint32_t)(((k + 1) % STAGES) * 8),
                                 ((k + 1) / STAGES) & 1);
            const uint32_t snoff = (uint32_t)(((k + 1) % STAGES) * STAGE_BYTES);
            #pragma unroll
            for (int p = 0; p < 4; p++)
                LDSM_X4(b0[p], bbase + snoff + c0 + p * (16 * 128));
        }
        MMA_BURST(b1);
    }

    // ---------------- Epilogue ----------------
    const float gam = __ldg(gamma_p);
    #pragma unroll
    for (int tm = 0; tm < 2; tm++) {
        const int m0 = mbase + wm * 32 + tm * 16 + (lid >> 2);
        const float x2a = g_x2[m0];
        const float x2b = g_x2[m0 + 8];
        #pragma unroll
        for (int nn = 0; nn < 8; nn++) {
            const int n0 = nbase + wn * 64 + nn * 8 + (lid & 3) * 2;
            const float y2a = g_y2[n0];
            const float y2b = g_y2[n0 + 1];
            const float* c = acc[tm][nn];
            float2 v0, v1;
            v0.x = __expf(-gam * fmaxf(x2a + y2a - 2.0f * c[0], 0.0f));
            v0.y = __expf(-gam * fmaxf(x2a + y2b - 2.0f * c[1], 0.0f));
            v1.x = __expf(-gam * fmaxf(x2b + y2a - 2.0f * c[2], 0.0f));
            v1.y = __expf(-gam * fmaxf(x2b + y2b - 2.0f * c[3], 0.0f));
            *reinterpret_cast<float2*>(out + (size_t)m0 * NYR + n0) = v0;
            *reinterpret_cast<float2*>(out + (size_t)(m0 + 8) * NYR + n0) = v1;
        }
    }
}

extern "C" void kernel_launch(void* const* d_in, const int* in_sizes, int n_in,
                              void* d_out, int out_size) {
    const float* x = (const float*)d_in[0];
    const float* y = (const float*)d_in[1];
    const float* gamma = (const float*)d_in[2];
    float* out = (float*)d_out;

    rbf_prep_kernel<<<NXR + NYR, 128>>>(x, y);

    cudaFuncSetAttribute(rbf_gemm_kernel,
                         cudaFuncAttributeMaxDynamicSharedMemorySize, SMEM_TOTAL);
    dim3 grid(NYR / TN, NXR / TM);
    rbf_gemm_kernel<<<grid, 256, SMEM_TOTAL>>>(out, gamma);
}